// round 13
// baseline (speedup 1.0000x reference)
#include <cuda_runtime.h>
#include <cuda_fp16.h>
#include <cstdint>

// ============================================================================
// Fully-fused Forecaster, v6: anti-phase warp ping-pong.
// One CTA owns 128 rows end-to-end (4 GEMM+LSTM stages + FC), fp16 MMA.
// Warps 0-7 (half0, rows 0-63): sweep(p) then epilogue(p).
// Warps 8-15 (half1, rows 64-127): epilogue(p-1) then sweep(p).
// => tensor pipe (sweeps) and MUFU pipe (epilogues) run concurrently.
// 3 B-buffer slots; one cp.async group per interval; wait_group 1 at end.
// Cell math / weights identical to the 203.5us R8 baseline.
// ============================================================================

#define NROWS 65536

__device__ __align__(16) __half d_W0i[512 * 64];
__device__ __align__(16) __half d_W0h[512 * 128];
__device__ __align__(16) __half d_W1i[512 * 128];
__device__ __align__(16) __half d_W1h[512 * 128];
__device__ float d_bias0p[512], d_bias1p[512];
__device__ float d_mug[64 * 512];
__device__ float d_fcw[128];
__device__ float d_fcb_v;
__device__ __align__(16) __half d_x16[NROWS * 64];

// ---------------- helpers ----------------
__device__ __forceinline__ uint32_t smem_u32(const void* p) {
    uint32_t a;
    asm("{ .reg .u64 t; cvta.to.shared.u64 t, %1; cvt.u32.u64 %0, t; }"
        : "=r"(a) : "l"(p));
    return a;
}
__device__ __forceinline__ void ldsm4(uint32_t* r, uint32_t a) {
    asm volatile("ldmatrix.sync.aligned.m8n8.x4.shared.b16 {%0,%1,%2,%3}, [%4];"
                 : "=r"(r[0]), "=r"(r[1]), "=r"(r[2]), "=r"(r[3]) : "r"(a));
}
__device__ __forceinline__ void mma16816(float* d, const uint32_t* a, const uint32_t* b) {
    asm volatile(
        "mma.sync.aligned.m16n8k16.row.col.f32.f16.f16.f32 "
        "{%0,%1,%2,%3}, {%4,%5,%6,%7}, {%8,%9}, {%0,%1,%2,%3};"
        : "+f"(d[0]), "+f"(d[1]), "+f"(d[2]), "+f"(d[3])
        : "r"(a[0]), "r"(a[1]), "r"(a[2]), "r"(a[3]), "r"(b[0]), "r"(b[1]));
}
#define CP_COMMIT() asm volatile("cp.async.commit_group;" ::: "memory")
#define CP_WAIT(n)  asm volatile("cp.async.wait_group %0;" :: "n"(n) : "memory")

__device__ __forceinline__ float sigm_f(float x) {
    return __fdividef(1.0f, 1.0f + __expf(-x));
}
__device__ __forceinline__ float tanh_f(float x) {
    return __fdividef(2.0f, 1.0f + __expf(-2.0f * x)) - 1.0f;
}

// packed-column mapping: c' -> (gate t, unit j)
__device__ __forceinline__ void cmap(int c_, int& gate, int& j) {
    int nc = c_ >> 7, cg = (c_ >> 5) & 3, t = (c_ >> 3) & 3, ct = c_ & 7;
    gate = t;
    j = nc * 32 + cg * 8 + ct;
}

// ============================================================================
// Prep kernels (identical to the R8 baseline)
// ============================================================================
__global__ void prep_pack(const float* __restrict__ Wih0, const float* __restrict__ Whh0,
                          const float* __restrict__ Wih1, const float* __restrict__ Whh1,
                          const float* __restrict__ bih0, const float* __restrict__ bhh0,
                          const float* __restrict__ bih1, const float* __restrict__ bhh1,
                          const float* __restrict__ fcw, const float* __restrict__ fcb) {
    int i = blockIdx.x * 256 + threadIdx.x;    // 65536 threads
    int c_ = i >> 7, k = i & 127;
    int gate, j;
    cmap(c_, gate, j);
    int G = gate * 128 + j;
    d_W0h[c_ * 128 + k] = __float2half_rn(Whh0[G * 128 + k]);
    d_W1i[c_ * 128 + k] = __float2half_rn(Wih1[G * 128 + k]);
    d_W1h[c_ * 128 + k] = __float2half_rn(Whh1[G * 128 + k]);
    if (k < 64) d_W0i[c_ * 64 + k] = __float2half_rn(Wih0[G * 64 + k]);
    if (k == 0) {
        d_bias0p[c_] = bih0[G] + bhh0[G];
        d_bias1p[c_] = bih1[G] + bhh1[G];
    }
    if (i < 128) d_fcw[i] = fcw[i];
    if (i == 0) d_fcb_v = fcb[0];
}

__global__ void prep_mug(const float* __restrict__ mu,
                         const float* __restrict__ Wih0,
                         const float* __restrict__ bih0,
                         const float* __restrict__ bhh0) {
    __shared__ float mur[64];
    int c_ = threadIdx.x;
    if (c_ < 64) mur[c_] = mu[blockIdx.x * 64 + c_];
    __syncthreads();
    int gate, j;
    cmap(c_, gate, j);
    int G = gate * 128 + j;
    float s = bih0[G] + bhh0[G];
    const float* wr = Wih0 + G * 64;
#pragma unroll
    for (int k = 0; k < 64; k++) s = fmaf(mur[k], wr[k], s);
    d_mug[blockIdx.x * 512 + c_] = s;
}

__global__ void prep_x(const float* __restrict__ x) {
    int i = blockIdx.x * 256 + threadIdx.x;
    float4 v = reinterpret_cast<const float4*>(x)[i];
    __half2 p01 = __floats2half2_rn(v.x, v.y);
    __half2 p23 = __floats2half2_rn(v.z, v.w);
    reinterpret_cast<uint2*>(d_x16)[i] =
        make_uint2(*reinterpret_cast<uint32_t*>(&p01), *reinterpret_cast<uint32_t*>(&p23));
}

// ============================================================================
// cp.async SMEM fill: 128 rows x KT fp16, stride ST = 2*KT+16
// ============================================================================
template <int KT>
__device__ __forceinline__ void cp_fill(uint32_t sdst, const __half* __restrict__ g,
                                        int row0, int tid) {
    constexpr int ST = KT * 2 + 16;
    constexpr int CPR = KT / 8;
    constexpr int ITER = 128 * CPR / 512;
#pragma unroll
    for (int t = 0; t < ITER; t++) {
        int e = tid + t * 512;
        int row = e / CPR;
        int kq = (e % CPR) * 8;
        uint32_t d = sdst + (uint32_t)row * ST + (uint32_t)kq * 2;
        const void* s = g + (size_t)(row0 + row) * KT + kq;
        asm volatile("cp.async.cg.shared.global [%0], [%1], 16;" :: "r"(d), "l"(s));
    }
}

// ============================================================================
// MMA sweep: warp tile 32 rows x 32 packed cols
// ============================================================================
template <int KT>
__device__ __forceinline__ void sweep(uint32_t sA, uint32_t sB, int lane,
                                      int m0, int n0, float (&acc)[2][4][4]) {
    constexpr int ST = KT * 2 + 16;
    const uint32_t lrow = (uint32_t)(lane & 15);
    const uint32_t lhi = (uint32_t)(lane >> 4) * 16u;
    const uint32_t aB0 = sA + (m0 + lrow) * ST + lhi;
    const uint32_t aB1 = aB0 + 16 * ST;
    const uint32_t bB0 = sB + (n0 + lrow) * ST + lhi;
    const uint32_t bB1 = bB0 + 16 * ST;
#pragma unroll
    for (int kc = 0; kc < KT / 16; kc++) {
        const uint32_t ko = kc * 32;
        uint32_t a0[4], a1[4], b0[4], b1[4];
        ldsm4(a0, aB0 + ko);
        ldsm4(a1, aB1 + ko);
        ldsm4(b0, bB0 + ko);
        ldsm4(b1, bB1 + ko);
        uint32_t be0[2] = {b0[0], b0[2]}, bo0[2] = {b0[1], b0[3]};
        uint32_t be1[2] = {b1[0], b1[2]}, bo1[2] = {b1[1], b1[3]};
        mma16816(acc[0][0], a0, be0); mma16816(acc[1][0], a1, be0);
        mma16816(acc[0][1], a0, bo0); mma16816(acc[1][1], a1, bo0);
        mma16816(acc[0][2], a0, be1); mma16816(acc[1][2], a1, be1);
        mma16816(acc[0][3], a0, bo1); mma16816(acc[1][3], a1, bo1);
    }
}

// ============================================================================
// Fused kernel
// ============================================================================
constexpr int ST128 = 272;
constexpr int TILE128 = 128 * ST128;   // 34816 B

__global__ void __launch_bounds__(512, 1) lstm_fused(float* __restrict__ out) {
    extern __shared__ __align__(128) char dsm[];
    __shared__ float s_b0[512], s_b1[512], s_mug[512], s_fcw[128];
    __shared__ float s_fc[4][128];

    const int tid = threadIdx.x, lane = tid & 31, wid = tid >> 5;
    const int hf = wid >> 3;                  // row-half: 0 or 1
    const int w8 = wid & 7;
    const int rg2 = w8 >> 2, cg = w8 & 3, q = lane & 3;
    const int m0 = hf * 64 + rg2 * 32;        // warp's row base within CTA
    const int n0 = cg * 32;
    const int row0 = blockIdx.x * 128;

    const uint32_t s0 = smem_u32(dsm);
    const uint32_t sH1 = s0, sH2 = s0 + TILE128, sH1p = s0 + 2 * TILE128;
    const uint32_t sX = sH1p;                 // overlay: x dead before h1p written
    const uint32_t sSL0 = s0 + 3 * TILE128;   // 3 B slots

    s_b0[tid] = d_bias0p[tid];
    s_b1[tid] = d_bias1p[tid];
    s_mug[tid] = d_mug[(row0 >> 10) * 512 + tid];
    if (tid < 128) s_fcw[tid] = d_fcw[tid];

    // prologue: G0 = x tile + phase0 B; G1 = phase1 B
    cp_fill<64>(sX, d_x16, row0, tid);
    cp_fill<64>(sSL0, d_W0i, 0, tid);
    CP_COMMIT();
    cp_fill<64>(sSL0 + TILE128, d_W0i + 128 * 64, 0, tid);
    CP_COMMIT();
    CP_WAIT(1);                               // G0 landed (own portion)

    uint32_t creg[4][4];                      // c as half2, [nc][mt*2+h2]
    float acc[2][4][4];
    float fcacc[4] = {0.0f, 0.0f, 0.0f, 0.0f};

    auto slot = [&](int p) -> uint32_t { return sSL0 + (uint32_t)(p % 3) * TILE128; };

    // prefetch B tile for global phase qp (0..19) into slot qp%3
    auto prefetch = [&](int qp) {
        if (qp >= 20) return;
        uint32_t dst = slot(qp);
        if (qp < 4)       cp_fill<64>(dst, d_W0i + qp * 128 * 64, 0, tid);
        else if (qp < 8)  cp_fill<128>(dst, d_W0h + (qp - 4) * 16384, 0, tid);
        else if (qp < 12) cp_fill<128>(dst, d_W1i + (qp - 8) * 16384, 0, tid);
        else {
            int t = qp - 12;
            cp_fill<128>(dst, ((t & 1) ? d_W1h : d_W1i) + (t >> 1) * 16384, 0, tid);
        }
        CP_COMMIT();
    };

    auto zacc = [&]() {
#pragma unroll
        for (int a = 0; a < 2; a++)
#pragma unroll
            for (int b = 0; b < 4; b++)
#pragma unroll
                for (int c = 0; c < 4; c++) acc[a][b][c] = 0.0f;
    };

    // epilogue: thread-local LSTM cell on current acc
    auto epi = [&](int MODE, const float* addv, uint32_t sDst, int nc) {
#pragma unroll
        for (int mt = 0; mt < 2; mt++) {
#pragma unroll
            for (int h2 = 0; h2 < 2; h2++) {
                const int rowL = m0 + mt * 16 + (lane >> 2) + h2 * 8;
                const int s = mt * 2 + h2;
                float cprev[2] = {0.0f, 0.0f};
                if (MODE == 2 || MODE == 4) {
                    __half2 cp2 = *reinterpret_cast<__half2*>(&creg[nc][s]);
                    cprev[0] = __low2float(cp2);
                    cprev[1] = __high2float(cp2);
                }
                float hv[2], cv[2];
#pragma unroll
                for (int u = 0; u < 2; u++) {
                    const int bcol = cg * 32 + 2 * q + u;
                    float gi = acc[mt][0][h2 * 2 + u] + addv[bcol];
                    float gf = acc[mt][1][h2 * 2 + u] + addv[bcol + 8];
                    float gg = acc[mt][2][h2 * 2 + u] + addv[bcol + 16];
                    float go = acc[mt][3][h2 * 2 + u] + addv[bcol + 24];
                    float cn;
                    if (MODE == 1 || MODE == 3)
                        cn = sigm_f(gi) * tanh_f(gg);
                    else
                        cn = sigm_f(gf) * cprev[u] + sigm_f(gi) * tanh_f(gg);
                    hv[u] = sigm_f(go) * tanh_f(cn);
                    cv[u] = cn;
                }
                if (MODE == 4) {
                    const int j0 = (0) * 32 + cg * 8 + 2 * q;   // fcw indexed by unit within chunk
                    fcacc[s] = fmaf(fmaxf(hv[0], 0.0f), s_fcw[nc * 32 + cg * 8 + 2 * q], fcacc[s]);
                    fcacc[s] = fmaf(fmaxf(hv[1], 0.0f), s_fcw[nc * 32 + cg * 8 + 2 * q + 1], fcacc[s]);
                    (void)j0;
                } else {
                    __half2 hh = __floats2half2_rn(hv[0], hv[1]);
                    uint32_t addr = sDst + (uint32_t)rowL * ST128
                                  + (uint32_t)(nc * 32 + cg * 8 + 2 * q) * 2;
                    asm volatile("st.shared.b32 [%0], %1;"
                                 :: "r"(addr), "r"(*reinterpret_cast<uint32_t*>(&hh)));
                    if (MODE == 1 || MODE == 3) {
                        __half2 cc = __floats2half2_rn(cv[0], cv[1]);
                        creg[nc][s] = *reinterpret_cast<uint32_t*>(&cc);
                    }
                }
            }
        }
    };

    // ---------------- stage 1 (phases 0..3): x -> h1, c1 ----------------
#pragma unroll
    for (int nc = 0; nc < 4; nc++) {
        __syncthreads();
        prefetch(nc + 2);
        if (hf == 0) {
            zacc();
            sweep<64>(sX, slot(nc), lane, m0, n0, acc);
            epi(1, s_b0 + nc * 128, sH1, nc);
        } else {
            if (nc > 0) epi(1, s_b0 + (nc - 1) * 128, sH1, nc - 1);
            zacc();
            sweep<64>(sX, slot(nc), lane, m0, n0, acc);
        }
        CP_WAIT(1);
    }

    // ---------------- stage 2 (phases 4..7): h1 -> h2 (uses c1) ----------------
#pragma unroll
    for (int nc = 0; nc < 4; nc++) {
        const int p = 4 + nc;
        __syncthreads();
        prefetch(p + 2);
        if (hf == 0) {
            zacc();
            sweep<128>(sH1, slot(p), lane, m0, n0, acc);
            epi(2, s_mug + nc * 128, sH2, nc);
        } else {
            if (nc == 0) {
                epi(1, s_b0 + 3 * 128, sH1, 3);      // deferred: finishes h1
                asm volatile("bar.sync 1, 256;" ::: "memory");  // half1: h1 ready
            } else {
                epi(2, s_mug + (nc - 1) * 128, sH2, nc - 1);
            }
            zacc();
            sweep<128>(sH1, slot(p), lane, m0, n0, acc);
        }
        CP_WAIT(1);
    }

    // ---------------- stage 3 (phases 8..11): h1 -> h1p, c1p ----------------
#pragma unroll
    for (int nc = 0; nc < 4; nc++) {
        const int p = 8 + nc;
        __syncthreads();
        prefetch(p + 2);
        if (hf == 0) {
            zacc();
            sweep<128>(sH1, slot(p), lane, m0, n0, acc);
            epi(3, s_b1 + nc * 128, sH1p, nc);
        } else {
            if (nc == 0) epi(2, s_mug + 3 * 128, sH2, 3);   // deferred (writes sH2; no reader yet)
            else         epi(3, s_b1 + (nc - 1) * 128, sH1p, nc - 1);
            zacc();
            sweep<128>(sH1, slot(p), lane, m0, n0, acc);
        }
        CP_WAIT(1);
    }

    // ---------------- stage 4 (phases 12..19): h2@W1i + h1p@W1h -> relu -> FC ----
#pragma unroll
    for (int t = 0; t < 8; t++) {
        const int p = 12 + t;
        __syncthreads();
        prefetch(p + 2);
        if (hf == 0) {
            if ((t & 1) == 0) zacc();
            sweep<128>((t & 1) ? sH1p : sH2, slot(p), lane, m0, n0, acc);
            if (t & 1) epi(4, s_b1 + (t >> 1) * 128, 0, t >> 1);
        } else {
            if (t == 0)            epi(3, s_b1 + 3 * 128, sH1p, 3);     // deferred
            else if ((t & 1) == 0) epi(4, s_b1 + (t / 2 - 1) * 128, 0, t / 2 - 1);
            if ((t & 1) == 0) zacc();
            sweep<128>((t & 1) ? sH1p : sH2, slot(p), lane, m0, n0, acc);
        }
        if (p < 18) { CP_WAIT(1); } else { CP_WAIT(0); }
    }
    if (hf == 1) epi(4, s_b1 + 3 * 128, 0, 3);   // tail deferred epilogue

    // ---- FC reduce ----
#pragma unroll
    for (int s = 0; s < 4; s++) {
        float v = fcacc[s];
        v += __shfl_xor_sync(0xffffffffu, v, 1);
        v += __shfl_xor_sync(0xffffffffu, v, 2);
        if (q == 0) {
            const int rowL = m0 + (s >> 1) * 16 + (lane >> 2) + (s & 1) * 8;
            s_fc[cg][rowL] = v;
        }
    }
    __syncthreads();
    if (tid < 128)
        out[row0 + tid] = s_fc[0][tid] + s_fc[1][tid] + s_fc[2][tid] + s_fc[3][tid] + d_fcb_v;
}

// ============================================================================
// Launch
// ============================================================================
extern "C" void kernel_launch(void* const* d_in, const int* in_sizes, int n_in,
                              void* d_out, int out_size) {
    const float* x    = (const float*)d_in[0];
    const float* mu   = (const float*)d_in[1];
    const float* Wih0 = (const float*)d_in[2];
    const float* Whh0 = (const float*)d_in[3];
    const float* bih0 = (const float*)d_in[4];
    const float* bhh0 = (const float*)d_in[5];
    const float* Wih1 = (const float*)d_in[6];
    const float* Whh1 = (const float*)d_in[7];
    const float* bih1 = (const float*)d_in[8];
    const float* bhh1 = (const float*)d_in[9];
    const float* fcw  = (const float*)d_in[10];
    const float* fcb  = (const float*)d_in[11];
    float* out = (float*)d_out;

    const int SMEM = 6 * TILE128;   // 3 state tiles + 3 B slots = 208896 B
    cudaFuncSetAttribute(lstm_fused, cudaFuncAttributeMaxDynamicSharedMemorySize, SMEM);

    prep_pack<<<256, 256>>>(Wih0, Whh0, Wih1, Whh1, bih0, bhh0, bih1, bhh1, fcw, fcb);
    prep_mug<<<64, 512>>>(mu, Wih0, bih0, bhh0);
    prep_x<<<4096, 256>>>(x);

    lstm_fused<<<512, 512, SMEM>>>(out);
}

// round 14
// speedup vs baseline: 1.0490x; 1.0490x over previous
#include <cuda_runtime.h>
#include <cuda_fp16.h>
#include <cstdint>

// ============================================================================
// Fully-fused Forecaster, v7: 64-row CTAs, 2 CTAs/SM (cross-CTA pipe overlap).
//   stage1: x  @ W0i (K=64)  + bias0 -> h1 (SMEM), c1 (regs)
//   stage2: h1 @ W0h (K=128) + mug   -> h2 (SMEM)          [c1 regs]
//   stage3: h1 @ W1i (K=128) + bias1 -> h1p (SMEM), c1p (regs)
//   stage4: h2 @ W1i + h1p @ W1h + bias1 -> relu -> FC -> out
// Single B buffer per CTA; the co-resident CTA hides fill latency and
// fills the idle pipe (its sweeps overlap our epilogues and vice versa).
// Cell math / weights identical to the 203.5us R8 baseline.
// ============================================================================

#define NROWS 65536

__device__ __align__(16) __half d_W0i[512 * 64];
__device__ __align__(16) __half d_W0h[512 * 128];
__device__ __align__(16) __half d_W1i[512 * 128];
__device__ __align__(16) __half d_W1h[512 * 128];
__device__ float d_bias0p[512], d_bias1p[512];
__device__ float d_mug[64 * 512];
__device__ float d_fcw[128];
__device__ float d_fcb_v;
__device__ __align__(16) __half d_x16[NROWS * 64];

// ---------------- helpers ----------------
__device__ __forceinline__ uint32_t smem_u32(const void* p) {
    uint32_t a;
    asm("{ .reg .u64 t; cvta.to.shared.u64 t, %1; cvt.u32.u64 %0, t; }"
        : "=r"(a) : "l"(p));
    return a;
}
__device__ __forceinline__ void ldsm4(uint32_t* r, uint32_t a) {
    asm volatile("ldmatrix.sync.aligned.m8n8.x4.shared.b16 {%0,%1,%2,%3}, [%4];"
                 : "=r"(r[0]), "=r"(r[1]), "=r"(r[2]), "=r"(r[3]) : "r"(a));
}
__device__ __forceinline__ void mma16816(float* d, const uint32_t* a, const uint32_t* b) {
    asm volatile(
        "mma.sync.aligned.m16n8k16.row.col.f32.f16.f16.f32 "
        "{%0,%1,%2,%3}, {%4,%5,%6,%7}, {%8,%9}, {%0,%1,%2,%3};"
        : "+f"(d[0]), "+f"(d[1]), "+f"(d[2]), "+f"(d[3])
        : "r"(a[0]), "r"(a[1]), "r"(a[2]), "r"(a[3]), "r"(b[0]), "r"(b[1]));
}
#define CP_COMMIT() asm volatile("cp.async.commit_group;" ::: "memory")
#define CP_WAIT0()  asm volatile("cp.async.wait_group 0;" ::: "memory")

__device__ __forceinline__ float sigm_f(float x) {
    return __fdividef(1.0f, 1.0f + __expf(-x));
}
__device__ __forceinline__ float tanh_f(float x) {
    return __fdividef(2.0f, 1.0f + __expf(-2.0f * x)) - 1.0f;
}

// packed-column mapping: c' -> (gate t, unit j)
__device__ __forceinline__ void cmap(int c_, int& gate, int& j) {
    int nc = c_ >> 7, cg = (c_ >> 5) & 3, t = (c_ >> 3) & 3, ct = c_ & 7;
    gate = t;
    j = nc * 32 + cg * 8 + ct;
}

// ============================================================================
// Prep kernels (identical to R8)
// ============================================================================
__global__ void prep_pack(const float* __restrict__ Wih0, const float* __restrict__ Whh0,
                          const float* __restrict__ Wih1, const float* __restrict__ Whh1,
                          const float* __restrict__ bih0, const float* __restrict__ bhh0,
                          const float* __restrict__ bih1, const float* __restrict__ bhh1,
                          const float* __restrict__ fcw, const float* __restrict__ fcb) {
    int i = blockIdx.x * 256 + threadIdx.x;    // 65536 threads
    int c_ = i >> 7, k = i & 127;
    int gate, j;
    cmap(c_, gate, j);
    int G = gate * 128 + j;
    d_W0h[c_ * 128 + k] = __float2half_rn(Whh0[G * 128 + k]);
    d_W1i[c_ * 128 + k] = __float2half_rn(Wih1[G * 128 + k]);
    d_W1h[c_ * 128 + k] = __float2half_rn(Whh1[G * 128 + k]);
    if (k < 64) d_W0i[c_ * 64 + k] = __float2half_rn(Wih0[G * 64 + k]);
    if (k == 0) {
        d_bias0p[c_] = bih0[G] + bhh0[G];
        d_bias1p[c_] = bih1[G] + bhh1[G];
    }
    if (i < 128) d_fcw[i] = fcw[i];
    if (i == 0) d_fcb_v = fcb[0];
}

__global__ void prep_mug(const float* __restrict__ mu,
                         const float* __restrict__ Wih0,
                         const float* __restrict__ bih0,
                         const float* __restrict__ bhh0) {
    __shared__ float mur[64];
    int c_ = threadIdx.x;
    if (c_ < 64) mur[c_] = mu[blockIdx.x * 64 + c_];
    __syncthreads();
    int gate, j;
    cmap(c_, gate, j);
    int G = gate * 128 + j;
    float s = bih0[G] + bhh0[G];
    const float* wr = Wih0 + G * 64;
#pragma unroll
    for (int k = 0; k < 64; k++) s = fmaf(mur[k], wr[k], s);
    d_mug[blockIdx.x * 512 + c_] = s;
}

__global__ void prep_x(const float* __restrict__ x) {
    int i = blockIdx.x * 256 + threadIdx.x;
    float4 v = reinterpret_cast<const float4*>(x)[i];
    __half2 p01 = __floats2half2_rn(v.x, v.y);
    __half2 p23 = __floats2half2_rn(v.z, v.w);
    reinterpret_cast<uint2*>(d_x16)[i] =
        make_uint2(*reinterpret_cast<uint32_t*>(&p01), *reinterpret_cast<uint32_t*>(&p23));
}

// ============================================================================
// cp.async SMEM fill: ROWS x KT fp16, stride ST = 2*KT+16, 256 threads
// ============================================================================
template <int KT, int ROWS>
__device__ __forceinline__ void cp_fill(uint32_t sdst, const __half* __restrict__ g,
                                        int row0, int tid) {
    constexpr int ST = KT * 2 + 16;
    constexpr int CPR = KT / 8;
    constexpr int ITER = ROWS * CPR / 256;
#pragma unroll
    for (int t = 0; t < ITER; t++) {
        int e = tid + t * 256;
        int row = e / CPR;
        int kq = (e % CPR) * 8;
        uint32_t d = sdst + (uint32_t)row * ST + (uint32_t)kq * 2;
        const void* s = g + (size_t)(row0 + row) * KT + kq;
        asm volatile("cp.async.cg.shared.global [%0], [%1], 16;" :: "r"(d), "l"(s));
    }
}

// ============================================================================
// MMA sweep: warp tile 32 rows x 32 packed cols
// ============================================================================
template <int KT>
__device__ __forceinline__ void sweep(uint32_t sA, uint32_t sB, int lane,
                                      int m0, int n0, float (&acc)[2][4][4]) {
    constexpr int ST = KT * 2 + 16;
    const uint32_t lrow = (uint32_t)(lane & 15);
    const uint32_t lhi = (uint32_t)(lane >> 4) * 16u;
    const uint32_t aB0 = sA + (m0 + lrow) * ST + lhi;
    const uint32_t aB1 = aB0 + 16 * ST;
    const uint32_t bB0 = sB + (n0 + lrow) * ST + lhi;
    const uint32_t bB1 = bB0 + 16 * ST;
#pragma unroll
    for (int kc = 0; kc < KT / 16; kc++) {
        const uint32_t ko = kc * 32;
        uint32_t a0[4], a1[4], b0[4], b1[4];
        ldsm4(a0, aB0 + ko);
        ldsm4(a1, aB1 + ko);
        ldsm4(b0, bB0 + ko);
        ldsm4(b1, bB1 + ko);
        uint32_t be0[2] = {b0[0], b0[2]}, bo0[2] = {b0[1], b0[3]};
        uint32_t be1[2] = {b1[0], b1[2]}, bo1[2] = {b1[1], b1[3]};
        mma16816(acc[0][0], a0, be0); mma16816(acc[1][0], a1, be0);
        mma16816(acc[0][1], a0, bo0); mma16816(acc[1][1], a1, bo0);
        mma16816(acc[0][2], a0, be1); mma16816(acc[1][2], a1, be1);
        mma16816(acc[0][3], a0, bo1); mma16816(acc[1][3], a1, bo1);
    }
}

// ============================================================================
// Fused kernel: 64 rows per CTA, 256 threads, 2 CTAs/SM
// ============================================================================
constexpr int ST128 = 272;
constexpr int ATILE = 64 * ST128;      // 17408 B (state tiles: 64 rows)
constexpr int BTILE = 128 * ST128;     // 34816 B (B: 128 packed cols)

__global__ void __launch_bounds__(256, 2) lstm_fused(float* __restrict__ out) {
    extern __shared__ __align__(128) char dsm[];
    __shared__ float s_b0[512], s_b1[512], s_mug[512], s_fcw[128];
    __shared__ float s_fc[4][64];

    const int tid = threadIdx.x, lane = tid & 31, wid = tid >> 5;
    const int rg = wid >> 2, cg = wid & 3, q = lane & 3;
    const int m0 = rg * 32, n0 = cg * 32;
    const int row0 = blockIdx.x * 64;

    const uint32_t s0 = smem_u32(dsm);
    const uint32_t sH1 = s0, sH2 = s0 + ATILE, sH1p = s0 + 2 * ATILE;
    const uint32_t sX = sH1p;                 // overlay: x dead before h1p written
    const uint32_t sB = s0 + 3 * ATILE;       // single B buffer

    s_b0[tid] = d_bias0p[tid];
    s_b0[tid + 256] = d_bias0p[tid + 256];
    s_b1[tid] = d_bias1p[tid];
    s_b1[tid + 256] = d_bias1p[tid + 256];
    s_mug[tid] = d_mug[(row0 >> 10) * 512 + tid];
    s_mug[tid + 256] = d_mug[(row0 >> 10) * 512 + tid + 256];
    if (tid < 128) s_fcw[tid] = d_fcw[tid];

    // prologue: x tile (joins phase-0 B fill group)
    cp_fill<64, 64>(sX, d_x16, row0, tid);

    uint32_t creg[4][4];                      // c as half2, [nc][mt*2+h2]
    float acc[2][4][4];
    float fcacc[4] = {0.0f, 0.0f, 0.0f, 0.0f};

    auto zacc = [&]() {
#pragma unroll
        for (int a = 0; a < 2; a++)
#pragma unroll
            for (int b = 0; b < 4; b++)
#pragma unroll
                for (int c = 0; c < 4; c++) acc[a][b][c] = 0.0f;
    };

    auto epi = [&](int MODE, const float* addv, uint32_t sDst, int nc) {
#pragma unroll
        for (int mt = 0; mt < 2; mt++) {
#pragma unroll
            for (int h2 = 0; h2 < 2; h2++) {
                const int rowL = m0 + mt * 16 + (lane >> 2) + h2 * 8;
                const int s = mt * 2 + h2;
                float cprev[2] = {0.0f, 0.0f};
                if (MODE == 2 || MODE == 4) {
                    __half2 cp2 = *reinterpret_cast<__half2*>(&creg[nc][s]);
                    cprev[0] = __low2float(cp2);
                    cprev[1] = __high2float(cp2);
                }
                float hv[2], cv[2];
#pragma unroll
                for (int u = 0; u < 2; u++) {
                    const int bcol = cg * 32 + 2 * q + u;
                    float gi = acc[mt][0][h2 * 2 + u] + addv[bcol];
                    float gf = acc[mt][1][h2 * 2 + u] + addv[bcol + 8];
                    float gg = acc[mt][2][h2 * 2 + u] + addv[bcol + 16];
                    float go = acc[mt][3][h2 * 2 + u] + addv[bcol + 24];
                    float cn;
                    if (MODE == 1 || MODE == 3)
                        cn = sigm_f(gi) * tanh_f(gg);
                    else
                        cn = sigm_f(gf) * cprev[u] + sigm_f(gi) * tanh_f(gg);
                    hv[u] = sigm_f(go) * tanh_f(cn);
                    cv[u] = cn;
                }
                if (MODE == 4) {
                    const int j0 = nc * 32 + cg * 8 + 2 * q;
                    fcacc[s] = fmaf(fmaxf(hv[0], 0.0f), s_fcw[j0], fcacc[s]);
                    fcacc[s] = fmaf(fmaxf(hv[1], 0.0f), s_fcw[j0 + 1], fcacc[s]);
                } else {
                    __half2 hh = __floats2half2_rn(hv[0], hv[1]);
                    uint32_t addr = sDst + (uint32_t)rowL * ST128
                                  + (uint32_t)(nc * 32 + cg * 8 + 2 * q) * 2;
                    asm volatile("st.shared.b32 [%0], %1;"
                                 :: "r"(addr), "r"(*reinterpret_cast<uint32_t*>(&hh)));
                    if (MODE == 1 || MODE == 3) {
                        __half2 cc = __floats2half2_rn(cv[0], cv[1]);
                        creg[nc][s] = *reinterpret_cast<uint32_t*>(&cc);
                    }
                }
            }
        }
    };

    // ---------------- 20 phases ----------------
#pragma unroll
    for (int p = 0; p < 20; p++) {
        // fill B for this phase (B slot free: prior sweep finished before the
        // closing __syncthreads of the previous phase)
        if (p < 4)       cp_fill<64, 128>(sB, d_W0i + p * 128 * 64, 0, tid);
        else if (p < 8)  cp_fill<128, 128>(sB, d_W0h + (p - 4) * 16384, 0, tid);
        else if (p < 12) cp_fill<128, 128>(sB, d_W1i + (p - 8) * 16384, 0, tid);
        else {
            const int t = p - 12;
            cp_fill<128, 128>(sB, ((t & 1) ? d_W1h : d_W1i) + (t >> 1) * 16384, 0, tid);
        }
        CP_COMMIT();
        CP_WAIT0();
        __syncthreads();                      // B (and stage inputs) ready

        if (p < 4) {                          // stage 1: x -> h1, c1
            zacc();
            sweep<64>(sX, sB, lane, m0, n0, acc);
            epi(1, s_b0 + p * 128, sH1, p);
        } else if (p < 8) {                   // stage 2: h1 -> h2 (c1)
            const int nc = p - 4;
            zacc();
            sweep<128>(sH1, sB, lane, m0, n0, acc);
            epi(2, s_mug + nc * 128, sH2, nc);
        } else if (p < 12) {                  // stage 3: h1 -> h1p, c1p
            const int nc = p - 8;
            zacc();
            sweep<128>(sH1, sB, lane, m0, n0, acc);
            epi(3, s_b1 + nc * 128, sH1p, nc);
        } else {                              // stage 4: h2@W1i + h1p@W1h
            const int t = p - 12;
            if ((t & 1) == 0) zacc();
            sweep<128>((t & 1) ? sH1p : sH2, sB, lane, m0, n0, acc);
            if (t & 1) epi(4, s_b1 + (t >> 1) * 128, 0, t >> 1);
        }
        __syncthreads();                      // all sweeps done -> B refillable
    }

    // ---- FC reduce ----
#pragma unroll
    for (int s = 0; s < 4; s++) {
        float v = fcacc[s];
        v += __shfl_xor_sync(0xffffffffu, v, 1);
        v += __shfl_xor_sync(0xffffffffu, v, 2);
        if (q == 0) {
            const int rowL = m0 + (s >> 1) * 16 + (lane >> 2) + (s & 1) * 8;
            s_fc[cg][rowL] = v;
        }
    }
    __syncthreads();
    if (tid < 64)
        out[row0 + tid] = s_fc[0][tid] + s_fc[1][tid] + s_fc[2][tid] + s_fc[3][tid] + d_fcb_v;
}

// ============================================================================
// Launch
// ============================================================================
extern "C" void kernel_launch(void* const* d_in, const int* in_sizes, int n_in,
                              void* d_out, int out_size) {
    const float* x    = (const float*)d_in[0];
    const float* mu   = (const float*)d_in[1];
    const float* Wih0 = (const float*)d_in[2];
    const float* Whh0 = (const float*)d_in[3];
    const float* bih0 = (const float*)d_in[4];
    const float* bhh0 = (const float*)d_in[5];
    const float* Wih1 = (const float*)d_in[6];
    const float* Whh1 = (const float*)d_in[7];
    const float* bih1 = (const float*)d_in[8];
    const float* bhh1 = (const float*)d_in[9];
    const float* fcw  = (const float*)d_in[10];
    const float* fcb  = (const float*)d_in[11];
    float* out = (float*)d_out;

    const int SMEM = 3 * ATILE + BTILE;   // 87040 B -> 2 CTAs/SM
    cudaFuncSetAttribute(lstm_fused, cudaFuncAttributeMaxDynamicSharedMemorySize, SMEM);

    prep_pack<<<256, 256>>>(Wih0, Whh0, Wih1, Whh1, bih0, bhh0, bih1, bhh1, fcw, fcb);
    prep_mug<<<64, 512>>>(mu, Wih0, bih0, bhh0);
    prep_x<<<4096, 256>>>(x);

    lstm_fused<<<1024, 256, SMEM>>>(out);
}